// round 4
// baseline (speedup 1.0000x reference)
#include <cuda_runtime.h>
#include <cuda_bf16.h>
#include <cstdint>

// ---------------------------------------------------------------------------
// Scratch (single static device buffer, offsets in floats)
// ---------------------------------------------------------------------------
#define OFF_A4    0              // 64*4899  = 313536
#define OFF_H1    313536         // 64*1000  = 64000
#define OFF_H2    377536         // 64*500   = 32000
#define OFF_DYNW  409536         // 64*9     = 576
#define OFF_Y1    410112         // 64*2*4900= 627200
#define OFF_CAT   1037312        // 64*15506 = 992384
#define OFF_Z1    2029696        // 64*8000  = 512000
#define OFF_Z2    2541696        // 64*2000  = 128000
#define OFF_PART  2669696        // up to 16*64*1000 / 2*64*8000 / 8*64*2000 = 1.024M
#define SCRATCH_FLOATS 3800000

__device__ float g_scratch[SCRATCH_FLOATS];

// ---------------------------------------------------------------------------
// TF32 helpers
// ---------------------------------------------------------------------------
__device__ __forceinline__ uint32_t f2tf(float x) {
    uint32_t r;
    asm("cvt.rna.tf32.f32 %0, %1;" : "=r"(r) : "f"(x));
    return r;
}

__device__ __forceinline__ void mma_tf32(float* c, const uint32_t* a,
                                         uint32_t b0, uint32_t b1) {
    asm("mma.sync.aligned.m16n8k8.row.col.f32.tf32.tf32.f32 "
        "{%0,%1,%2,%3},{%4,%5,%6,%7},{%8,%9},{%0,%1,%2,%3};"
        : "+f"(c[0]), "+f"(c[1]), "+f"(c[2]), "+f"(c[3])
        : "r"(a[0]), "r"(a[1]), "r"(a[2]), "r"(a[3]), "r"(b0), "r"(b1));
}

// ---------------------------------------------------------------------------
// GEMM: C_part[s] = A(64 x K) @ B(K x N), row-major both.
// 256 threads = 8 warps. Warp computes all 64 rows x 16 cols (2 n8-tiles).
// CTA covers 128 cols. gridDim.y = splitK; each split writes its own
// disjoint partial slab (deterministic, no atomics).
// SPLIT=true: 3-term split-TF32 (near-fp32 accuracy).
// ---------------------------------------------------------------------------
template <bool SPLIT>
__global__ __launch_bounds__(256) void gemm64(
    const float* __restrict__ A, const float* __restrict__ B,
    float* __restrict__ part, int K, int N, int splitk)
{
    const int warp = threadIdx.x >> 5;
    const int lane = threadIdx.x & 31;
    const int grp  = lane >> 2;      // 0..7
    const int qid  = lane & 3;       // 0..3
    const int nb   = blockIdx.x * 128 + warp * 16;
    const int s    = blockIdx.y;
    const int kchunk = (K + splitk - 1) / splitk;
    const int k0 = s * kchunk;
    const int k1 = min(K, k0 + kchunk);

    float acc[4][2][4];
#pragma unroll
    for (int t = 0; t < 4; t++)
#pragma unroll
        for (int j = 0; j < 2; j++)
#pragma unroll
            for (int i = 0; i < 4; i++) acc[t][j][i] = 0.f;

    const int n0 = nb + grp;
    const int n1 = nb + 8 + grp;
    const bool pn0 = n0 < N;
    const bool pn1 = n1 < N;

    for (int kk = k0; kk < k1; kk += 8) {
        const int c0 = kk + qid;
        const int c1 = c0 + 4;
        const bool p0 = c0 < k1;
        const bool p1 = c1 < k1;

        // ---- B fragment loads (streaming; 100% sector efficiency) ----
        float fb[2][2];
        fb[0][0] = (p0 && pn0) ? B[(size_t)c0 * N + n0] : 0.f;
        fb[0][1] = (p1 && pn0) ? B[(size_t)c1 * N + n0] : 0.f;
        fb[1][0] = (p0 && pn1) ? B[(size_t)c0 * N + n1] : 0.f;
        fb[1][1] = (p1 && pn1) ? B[(size_t)c1 * N + n1] : 0.f;

        // ---- A fragment loads (L2-resident activations) ----
        float fa[4][4];
#pragma unroll
        for (int t = 0; t < 4; t++) {
            const float* Ar = A + (size_t)(t * 16 + grp) * K;
            fa[t][0] = p0 ? Ar[c0]         : 0.f;
            fa[t][1] = p0 ? Ar[8 * (size_t)K + c0] : 0.f;
            fa[t][2] = p1 ? Ar[c1]         : 0.f;
            fa[t][3] = p1 ? Ar[8 * (size_t)K + c1] : 0.f;
        }

        uint32_t bhi[2][2], ahi[4][4];
#pragma unroll
        for (int j = 0; j < 2; j++) {
            bhi[j][0] = f2tf(fb[j][0]);
            bhi[j][1] = f2tf(fb[j][1]);
        }
#pragma unroll
        for (int t = 0; t < 4; t++)
#pragma unroll
            for (int i = 0; i < 4; i++) ahi[t][i] = f2tf(fa[t][i]);

        if (SPLIT) {
            uint32_t blo[2][2], alo[4][4];
#pragma unroll
            for (int j = 0; j < 2; j++)
#pragma unroll
                for (int i = 0; i < 2; i++)
                    blo[j][i] = f2tf(fb[j][i] - __uint_as_float(bhi[j][i]));
#pragma unroll
            for (int t = 0; t < 4; t++)
#pragma unroll
                for (int i = 0; i < 4; i++)
                    alo[t][i] = f2tf(fa[t][i] - __uint_as_float(ahi[t][i]));
#pragma unroll
            for (int t = 0; t < 4; t++) {
#pragma unroll
                for (int j = 0; j < 2; j++) {
                    mma_tf32(acc[t][j], alo[t], bhi[j][0], bhi[j][1]);
                    mma_tf32(acc[t][j], ahi[t], blo[j][0], blo[j][1]);
                    mma_tf32(acc[t][j], ahi[t], bhi[j][0], bhi[j][1]);
                }
            }
        } else {
#pragma unroll
            for (int t = 0; t < 4; t++)
#pragma unroll
                for (int j = 0; j < 2; j++)
                    mma_tf32(acc[t][j], ahi[t], bhi[j][0], bhi[j][1]);
        }
    }

    // ---- store partials ----
#pragma unroll
    for (int t = 0; t < 4; t++) {
#pragma unroll
        for (int j = 0; j < 2; j++) {
            const int col = nb + 8 * j + 2 * qid;
            const int row = t * 16 + grp;
            float* p = part + (size_t)(s * 64 + row) * N + col;
            if (col < N) {
                p[0]               = acc[t][j][0];
                p[(size_t)8 * N]   = acc[t][j][2];
            }
            if (col + 1 < N) {
                p[1]                 = acc[t][j][1];
                p[(size_t)8 * N + 1] = acc[t][j][3];
            }
        }
    }
}

// Reduce splitK partials + bias (+ReLU)
__global__ void epilogue(const float* __restrict__ part,
                         const float* __restrict__ bias,
                         float* __restrict__ out, int N, int splitk, int do_relu)
{
    int idx = blockIdx.x * blockDim.x + threadIdx.x;
    if (idx >= 64 * N) return;
    int row = idx / N, col = idx - row * N;
    float s = bias[col];
    for (int p = 0; p < splitk; p++)
        s += part[(size_t)(p * 64 + row) * N + col];
    out[idx] = do_relu ? fmaxf(s, 0.f) : s;
}

// ---------------------------------------------------------------------------
// Elementwise / small kernels
// ---------------------------------------------------------------------------

// 3x3 conv at (h, wpos) over a 2x4900 image with pad 1
__device__ __forceinline__ float conv3(const float* X, const float* w,
                                       float bias, int h, int wpos)
{
    float s = bias;
#pragma unroll
    for (int dh = 0; dh < 3; dh++) {
        int ih = h + dh - 1;
        if (ih < 0 || ih > 1) continue;
        const float* R = X + ih * 4900;
#pragma unroll
        for (int dw = 0; dw < 3; dw++) {
            int iw = wpos + dw - 1;
            if (iw >= 0 && iw < 4900) s += R[iw] * w[dh * 3 + dw];
        }
    }
    return s;
}

// branch a front: conv(w1,pad1)+b1 -> relu -> maxpool 2x2 s1 -> A4 (64,4899)
__global__ void k_a_front(const float* __restrict__ x1,
                          const float* __restrict__ w1,
                          const float* __restrict__ b1,
                          float* __restrict__ A4)
{
    int j = blockIdx.x * blockDim.x + threadIdx.x;
    int b = blockIdx.y;
    if (j >= 4899) return;
    const float* X = x1 + (size_t)b * 9800;
    float w[9];
#pragma unroll
    for (int i = 0; i < 9; i++) w[i] = w1[i];
    float bias = b1[0];
    float m = conv3(X, w, bias, 0, j);
    m = fmaxf(m, conv3(X, w, bias, 0, j + 1));
    m = fmaxf(m, conv3(X, w, bias, 1, j));
    m = fmaxf(m, conv3(X, w, bias, 1, j + 1));
    A4[(size_t)b * 4899 + j] = fmaxf(m, 0.f);
}

// a3 = h2 @ Wc + bc ; dynw = lw * a3   (64 x 9 outputs, K=500)
__global__ void k_dynw(const float* __restrict__ h2,
                       const float* __restrict__ Wc,
                       const float* __restrict__ bc,
                       const float* __restrict__ lw,
                       float* __restrict__ dynw)
{
    int t = blockIdx.x * blockDim.x + threadIdx.x;
    if (t >= 64 * 9) return;
    int b = t / 9, i = t - b * 9;
    const float* H = h2 + b * 500;
    float s = bc[i];
    for (int k = 0; k < 500; k++) s += H[k] * Wc[k * 9 + i];
    dynw[t] = s * lw[t];
}

// per-sample dynamic 3x3 conv + lb -> relu -> maxpool 2x2 s2 -> cat[:, 0:2450]
__global__ void k_dynconv(const float* __restrict__ x1,
                          const float* __restrict__ dynw,
                          const float* __restrict__ lb,
                          float* __restrict__ cat)
{
    int j = blockIdx.x * blockDim.x + threadIdx.x;
    int b = blockIdx.y;
    if (j >= 2450) return;
    const float* X = x1 + (size_t)b * 9800;
    float w[9];
#pragma unroll
    for (int i = 0; i < 9; i++) w[i] = dynw[b * 9 + i];
    float bias = lb[b];
    float m = conv3(X, w, bias, 0, 2 * j);
    m = fmaxf(m, conv3(X, w, bias, 0, 2 * j + 1));
    m = fmaxf(m, conv3(X, w, bias, 1, 2 * j));
    m = fmaxf(m, conv3(X, w, bias, 1, 2 * j + 1));
    cat[(size_t)b * 15506 + j] = fmaxf(m, 0.f);
}

// 2x2 conv at (hh in 0..2, ww in 0..4900) over 2x4900 image, pad 1
__device__ __forceinline__ float conv2x2(const float* X, const float* w,
                                         float bias, int hh, int ww)
{
    float s = bias;
#pragma unroll
    for (int dh = 0; dh < 2; dh++) {
        int ih = hh - 1 + dh;
        if (ih < 0 || ih > 1) continue;
        const float* R = X + ih * 4900;
#pragma unroll
        for (int dw = 0; dw < 2; dw++) {
            int iw = ww - 1 + dw;
            if (iw >= 0 && iw < 4900) s += R[iw] * w[dh * 2 + dw];
        }
    }
    return s;
}

// branch b stage 1: conv(w5,pad1)+b5 -> relu -> maxpool 2x2 s1 -> y1 (64,2,4900)
__global__ void k_b1(const float* __restrict__ x2,
                     const float* __restrict__ w5,
                     const float* __restrict__ b5,
                     float* __restrict__ y1)
{
    int idx = blockIdx.x * blockDim.x + threadIdx.x;
    int b = blockIdx.y;
    if (idx >= 9800) return;
    int h = idx / 4900, w = idx - h * 4900;
    const float* X = x2 + (size_t)b * 9800;
    float wk[4];
#pragma unroll
    for (int i = 0; i < 4; i++) wk[i] = w5[i];
    float bias = b5[0];
    float m = conv2x2(X, wk, bias, h, w);
    m = fmaxf(m, conv2x2(X, wk, bias, h, w + 1));
    m = fmaxf(m, conv2x2(X, wk, bias, h + 1, w));
    m = fmaxf(m, conv2x2(X, wk, bias, h + 1, w + 1));
    y1[(size_t)b * 9800 + idx] = fmaxf(m, 0.f);
}

// branch b stage 2: conv(w6, s2)+b6 -> relu -> maxpool (1,6) s6 -> cat[:, 2450:]
__global__ void k_b2(const float* __restrict__ y1,
                     const float* __restrict__ w6,
                     const float* __restrict__ b6,
                     float* __restrict__ cat)
{
    int t = blockIdx.x * blockDim.x + threadIdx.x;
    int b = blockIdx.y;
    if (t >= 32 * 408) return;
    int c = t / 408, j = t - c * 408;
    float w0 = w6[c * 4 + 0], w1v = w6[c * 4 + 1];
    float w2 = w6[c * 4 + 2], w3 = w6[c * 4 + 3];
    float bias = b6[c];
    const float* Y0 = y1 + (size_t)b * 9800;
    const float* Y1 = Y0 + 4900;
    float m = -3.4e38f;
#pragma unroll
    for (int tt = 0; tt < 6; tt++) {
        int wp = 6 * j + tt;  // <= 2447 < 2450
        float s = bias + Y0[2 * wp] * w0 + Y0[2 * wp + 1] * w1v
                       + Y1[2 * wp] * w2 + Y1[2 * wp + 1] * w3;
        m = fmaxf(m, s);
    }
    cat[(size_t)b * 15506 + 2450 + t] = fmaxf(m, 0.f);
}

// final: out(64,2) = z2(64,2000) @ Wf3(2000,2) + bf3 (exact fp32 block-reduce)
__global__ void k_final(const float* __restrict__ z2,
                        const float* __restrict__ Wf3,
                        const float* __restrict__ bf3,
                        float* __restrict__ out)
{
    int b = blockIdx.x >> 1;
    int c = blockIdx.x & 1;
    const float* Z = z2 + b * 2000;
    float s = 0.f;
    for (int k = threadIdx.x; k < 2000; k += 128)
        s += Z[k] * Wf3[2 * k + c];
    __shared__ float red[128];
    red[threadIdx.x] = s;
    __syncthreads();
    for (int d = 64; d > 0; d >>= 1) {
        if (threadIdx.x < d) red[threadIdx.x] += red[threadIdx.x + d];
        __syncthreads();
    }
    if (threadIdx.x == 0) out[b * 2 + c] = red[0] + bf3[c];
}

// ---------------------------------------------------------------------------
// launch
// ---------------------------------------------------------------------------
extern "C" void kernel_launch(void* const* d_in, const int* in_sizes, int n_in,
                              void* d_out, int out_size)
{
    const float* x1  = (const float*)d_in[0];
    const float* x2  = (const float*)d_in[1];
    const float* w1  = (const float*)d_in[2];
    const float* b1  = (const float*)d_in[3];
    const float* Wa  = (const float*)d_in[4];
    const float* ba  = (const float*)d_in[5];
    const float* Wb  = (const float*)d_in[6];
    const float* bb  = (const float*)d_in[7];
    const float* Wc  = (const float*)d_in[8];
    const float* bc  = (const float*)d_in[9];
    const float* lw  = (const float*)d_in[10];
    const float* lb  = (const float*)d_in[11];
    const float* w5  = (const float*)d_in[12];
    const float* b5  = (const float*)d_in[13];
    const float* w6  = (const float*)d_in[14];
    const float* b6  = (const float*)d_in[15];
    const float* Wf1 = (const float*)d_in[16];
    const float* bf1 = (const float*)d_in[17];
    const float* Wf2 = (const float*)d_in[18];
    const float* bf2 = (const float*)d_in[19];
    const float* Wf3 = (const float*)d_in[20];
    const float* bf3 = (const float*)d_in[21];
    float* out = (float*)d_out;

    float* S = nullptr;
    cudaGetSymbolAddress((void**)&S, g_scratch);
    float* A4   = S + OFF_A4;
    float* h1   = S + OFF_H1;
    float* h2   = S + OFF_H2;
    float* dynw = S + OFF_DYNW;
    float* y1   = S + OFF_Y1;
    float* cat  = S + OFF_CAT;
    float* z1   = S + OFF_Z1;
    float* z2   = S + OFF_Z2;
    float* part = S + OFF_PART;

    // branch a front
    k_a_front<<<dim3(20, 64), 256>>>(x1, w1, b1, A4);

    // h1 = relu(A4 @ Wa + ba)   [K=4899, N=1000] split-tf32, splitK=16
    gemm64<true><<<dim3(8, 16), 256>>>(A4, Wa, part, 4899, 1000, 16);
    epilogue<<<(64 * 1000 + 255) / 256, 256>>>(part, ba, h1, 1000, 16, 1);

    // h2 = relu(h1 @ Wb + bb)   [K=1000, N=500] split-tf32, splitK=16
    gemm64<true><<<dim3(4, 16), 256>>>(h1, Wb, part, 1000, 500, 16);
    epilogue<<<(64 * 500 + 255) / 256, 256>>>(part, bb, h2, 500, 16, 1);

    // dynamic weights + per-sample conv -> cat[:, 0:2450]
    k_dynw<<<3, 256>>>(h2, Wc, bc, lw, dynw);
    k_dynconv<<<dim3(10, 64), 256>>>(x1, dynw, lb, cat);

    // branch b -> cat[:, 2450:]
    k_b1<<<dim3(39, 64), 256>>>(x2, w5, b5, y1);
    k_b2<<<dim3(51, 64), 256>>>(y1, w6, b6, cat);

    // z1 = relu(cat @ Wf1 + bf1) [K=15506, N=8000] single tf32, splitK=2
    gemm64<false><<<dim3(63, 2), 256>>>(cat, Wf1, part, 15506, 8000, 2);
    epilogue<<<(64 * 8000 + 255) / 256, 256>>>(part, bf1, z1, 8000, 2, 1);

    // z2 = relu(z1 @ Wf2 + bf2)  [K=8000, N=2000] split-tf32, splitK=8
    gemm64<true><<<dim3(16, 8), 256>>>(z1, Wf2, part, 8000, 2000, 8);
    epilogue<<<(64 * 2000 + 255) / 256, 256>>>(part, bf2, z2, 2000, 8, 1);

    // out = z2 @ Wf3 + bf3
    k_final<<<128, 128>>>(z2, Wf3, bf3, out);
}

// round 6
// speedup vs baseline: 1.0099x; 1.0099x over previous
#include <cuda_runtime.h>
#include <cuda_bf16.h>
#include <cstdint>

// ---------------------------------------------------------------------------
// Scratch (single static device buffer, offsets in floats)
// ---------------------------------------------------------------------------
#define OFF_A4    0              // 64*4899  = 313536
#define OFF_H1    313536         // 64*1000  = 64000
#define OFF_H2    377536         // 64*500   = 32000
#define OFF_DYNW  409536         // 64*9     = 576
#define OFF_Y1    410112         // 64*2*4900= 627200
#define OFF_CAT   1037312        // 64*15506 = 992384
#define OFF_Z1    2029696        // 64*8000  = 512000
#define OFF_Z2    2541696        // 64*2000  = 128000
#define OFF_PART  2669696        // up to 16*64*1000 / 2*64*8000 / 8*64*2000 = 1.024M
#define SCRATCH_FLOATS 3800000

__device__ float g_scratch[SCRATCH_FLOATS];

// ---------------------------------------------------------------------------
// TF32 helpers
// ---------------------------------------------------------------------------
__device__ __forceinline__ uint32_t f2tf(float x) {
    uint32_t r;
    asm("cvt.rna.tf32.f32 %0, %1;" : "=r"(r) : "f"(x));
    return r;
}

__device__ __forceinline__ void mma_tf32(float* c, const uint32_t* a,
                                         uint32_t b0, uint32_t b1) {
    asm("mma.sync.aligned.m16n8k8.row.col.f32.tf32.tf32.f32 "
        "{%0,%1,%2,%3},{%4,%5,%6,%7},{%8,%9},{%0,%1,%2,%3};"
        : "+f"(c[0]), "+f"(c[1]), "+f"(c[2]), "+f"(c[3])
        : "r"(a[0]), "r"(a[1]), "r"(a[2]), "r"(a[3]), "r"(b0), "r"(b1));
}

// ---------------------------------------------------------------------------
// GEMM: C_part[s] = A(64 x K) @ B(K x N), row-major both.
// 256 threads = 8 warps. Warp computes all 64 rows x 16 cols (2 n8-tiles).
// CTA covers 128 cols. gridDim.y = splitK; each split writes its own
// disjoint partial slab (deterministic, no atomics).
// SPLIT=true: 3-term split-TF32 (near-fp32 accuracy).
// ---------------------------------------------------------------------------
template <bool SPLIT>
__global__ __launch_bounds__(256) void gemm64(
    const float* __restrict__ A, const float* __restrict__ B,
    float* __restrict__ part, int K, int N, int splitk)
{
    const int warp = threadIdx.x >> 5;
    const int lane = threadIdx.x & 31;
    const int grp  = lane >> 2;      // 0..7
    const int qid  = lane & 3;       // 0..3
    const int nb   = blockIdx.x * 128 + warp * 16;
    const int s    = blockIdx.y;
    const int kchunk = (K + splitk - 1) / splitk;
    const int k0 = s * kchunk;
    const int k1 = min(K, k0 + kchunk);

    float acc[4][2][4];
#pragma unroll
    for (int t = 0; t < 4; t++)
#pragma unroll
        for (int j = 0; j < 2; j++)
#pragma unroll
            for (int i = 0; i < 4; i++) acc[t][j][i] = 0.f;

    const int n0 = nb + grp;
    const int n1 = nb + 8 + grp;
    const bool pn0 = n0 < N;
    const bool pn1 = n1 < N;

    for (int kk = k0; kk < k1; kk += 8) {
        const int c0 = kk + qid;
        const int c1 = c0 + 4;
        const bool p0 = c0 < k1;
        const bool p1 = c1 < k1;

        // ---- B fragment loads (streaming; 100% sector efficiency) ----
        float fb[2][2];
        fb[0][0] = (p0 && pn0) ? B[(size_t)c0 * N + n0] : 0.f;
        fb[0][1] = (p1 && pn0) ? B[(size_t)c1 * N + n0] : 0.f;
        fb[1][0] = (p0 && pn1) ? B[(size_t)c0 * N + n1] : 0.f;
        fb[1][1] = (p1 && pn1) ? B[(size_t)c1 * N + n1] : 0.f;

        // ---- A fragment loads (L2-resident activations) ----
        float fa[4][4];
#pragma unroll
        for (int t = 0; t < 4; t++) {
            const float* Ar = A + (size_t)(t * 16 + grp) * K;
            fa[t][0] = p0 ? Ar[c0]         : 0.f;
            fa[t][1] = p0 ? Ar[8 * (size_t)K + c0] : 0.f;
            fa[t][2] = p1 ? Ar[c1]         : 0.f;
            fa[t][3] = p1 ? Ar[8 * (size_t)K + c1] : 0.f;
        }

        uint32_t bhi[2][2], ahi[4][4];
#pragma unroll
        for (int j = 0; j < 2; j++) {
            bhi[j][0] = f2tf(fb[j][0]);
            bhi[j][1] = f2tf(fb[j][1]);
        }
#pragma unroll
        for (int t = 0; t < 4; t++)
#pragma unroll
            for (int i = 0; i < 4; i++) ahi[t][i] = f2tf(fa[t][i]);

        if (SPLIT) {
            uint32_t blo[2][2], alo[4][4];
#pragma unroll
            for (int j = 0; j < 2; j++)
#pragma unroll
                for (int i = 0; i < 2; i++)
                    blo[j][i] = f2tf(fb[j][i] - __uint_as_float(bhi[j][i]));
#pragma unroll
            for (int t = 0; t < 4; t++)
#pragma unroll
                for (int i = 0; i < 4; i++)
                    alo[t][i] = f2tf(fa[t][i] - __uint_as_float(ahi[t][i]));
#pragma unroll
            for (int t = 0; t < 4; t++) {
#pragma unroll
                for (int j = 0; j < 2; j++) {
                    mma_tf32(acc[t][j], alo[t], bhi[j][0], bhi[j][1]);
                    mma_tf32(acc[t][j], ahi[t], blo[j][0], blo[j][1]);
                    mma_tf32(acc[t][j], ahi[t], bhi[j][0], bhi[j][1]);
                }
            }
        } else {
#pragma unroll
            for (int t = 0; t < 4; t++)
#pragma unroll
                for (int j = 0; j < 2; j++)
                    mma_tf32(acc[t][j], ahi[t], bhi[j][0], bhi[j][1]);
        }
    }

    // ---- store partials ----
#pragma unroll
    for (int t = 0; t < 4; t++) {
#pragma unroll
        for (int j = 0; j < 2; j++) {
            const int col = nb + 8 * j + 2 * qid;
            const int row = t * 16 + grp;
            float* p = part + (size_t)(s * 64 + row) * N + col;
            if (col < N) {
                p[0]               = acc[t][j][0];
                p[(size_t)8 * N]   = acc[t][j][2];
            }
            if (col + 1 < N) {
                p[1]                 = acc[t][j][1];
                p[(size_t)8 * N + 1] = acc[t][j][3];
            }
        }
    }
}

// Reduce splitK partials + bias (+ReLU)
__global__ void epilogue(const float* __restrict__ part,
                         const float* __restrict__ bias,
                         float* __restrict__ out, int N, int splitk, int do_relu)
{
    int idx = blockIdx.x * blockDim.x + threadIdx.x;
    if (idx >= 64 * N) return;
    int row = idx / N, col = idx - row * N;
    float s = bias[col];
    for (int p = 0; p < splitk; p++)
        s += part[(size_t)(p * 64 + row) * N + col];
    out[idx] = do_relu ? fmaxf(s, 0.f) : s;
}

// ---------------------------------------------------------------------------
// Elementwise / small kernels
// ---------------------------------------------------------------------------

// 3x3 conv at (h, wpos) over a 2x4900 image with pad 1
__device__ __forceinline__ float conv3(const float* X, const float* w,
                                       float bias, int h, int wpos)
{
    float s = bias;
#pragma unroll
    for (int dh = 0; dh < 3; dh++) {
        int ih = h + dh - 1;
        if (ih < 0 || ih > 1) continue;
        const float* R = X + ih * 4900;
#pragma unroll
        for (int dw = 0; dw < 3; dw++) {
            int iw = wpos + dw - 1;
            if (iw >= 0 && iw < 4900) s += R[iw] * w[dh * 3 + dw];
        }
    }
    return s;
}

// branch a front: conv(w1,pad1)+b1 -> relu -> maxpool 2x2 s1 -> A4 (64,4899)
__global__ void k_a_front(const float* __restrict__ x1,
                          const float* __restrict__ w1,
                          const float* __restrict__ b1,
                          float* __restrict__ A4)
{
    int j = blockIdx.x * blockDim.x + threadIdx.x;
    int b = blockIdx.y;
    if (j >= 4899) return;
    const float* X = x1 + (size_t)b * 9800;
    float w[9];
#pragma unroll
    for (int i = 0; i < 9; i++) w[i] = w1[i];
    float bias = b1[0];
    float m = conv3(X, w, bias, 0, j);
    m = fmaxf(m, conv3(X, w, bias, 0, j + 1));
    m = fmaxf(m, conv3(X, w, bias, 1, j));
    m = fmaxf(m, conv3(X, w, bias, 1, j + 1));
    A4[(size_t)b * 4899 + j] = fmaxf(m, 0.f);
}

// a3 = h2 @ Wc + bc ; dynw = lw * a3   (64 x 9 outputs, K=500)
__global__ void k_dynw(const float* __restrict__ h2,
                       const float* __restrict__ Wc,
                       const float* __restrict__ bc,
                       const float* __restrict__ lw,
                       float* __restrict__ dynw)
{
    int t = blockIdx.x * blockDim.x + threadIdx.x;
    if (t >= 64 * 9) return;
    int b = t / 9, i = t - b * 9;
    const float* H = h2 + b * 500;
    float s = bc[i];
    for (int k = 0; k < 500; k++) s += H[k] * Wc[k * 9 + i];
    dynw[t] = s * lw[t];
}

// per-sample dynamic 3x3 conv + lb -> relu -> maxpool 2x2 s2 -> cat[:, 0:2450]
__global__ void k_dynconv(const float* __restrict__ x1,
                          const float* __restrict__ dynw,
                          const float* __restrict__ lb,
                          float* __restrict__ cat)
{
    int j = blockIdx.x * blockDim.x + threadIdx.x;
    int b = blockIdx.y;
    if (j >= 2450) return;
    const float* X = x1 + (size_t)b * 9800;
    float w[9];
#pragma unroll
    for (int i = 0; i < 9; i++) w[i] = dynw[b * 9 + i];
    float bias = lb[b];
    float m = conv3(X, w, bias, 0, 2 * j);
    m = fmaxf(m, conv3(X, w, bias, 0, 2 * j + 1));
    m = fmaxf(m, conv3(X, w, bias, 1, 2 * j));
    m = fmaxf(m, conv3(X, w, bias, 1, 2 * j + 1));
    cat[(size_t)b * 15506 + j] = fmaxf(m, 0.f);
}

// 2x2 conv at (hh in 0..2, ww in 0..4900) over 2x4900 image, pad 1
__device__ __forceinline__ float conv2x2(const float* X, const float* w,
                                         float bias, int hh, int ww)
{
    float s = bias;
#pragma unroll
    for (int dh = 0; dh < 2; dh++) {
        int ih = hh - 1 + dh;
        if (ih < 0 || ih > 1) continue;
        const float* R = X + ih * 4900;
#pragma unroll
        for (int dw = 0; dw < 2; dw++) {
            int iw = ww - 1 + dw;
            if (iw >= 0 && iw < 4900) s += R[iw] * w[dh * 2 + dw];
        }
    }
    return s;
}

// branch b stage 1: conv(w5,pad1)+b5 -> relu -> maxpool 2x2 s1 -> y1 (64,2,4900)
__global__ void k_b1(const float* __restrict__ x2,
                     const float* __restrict__ w5,
                     const float* __restrict__ b5,
                     float* __restrict__ y1)
{
    int idx = blockIdx.x * blockDim.x + threadIdx.x;
    int b = blockIdx.y;
    if (idx >= 9800) return;
    int h = idx / 4900, w = idx - h * 4900;
    const float* X = x2 + (size_t)b * 9800;
    float wk[4];
#pragma unroll
    for (int i = 0; i < 4; i++) wk[i] = w5[i];
    float bias = b5[0];
    float m = conv2x2(X, wk, bias, h, w);
    m = fmaxf(m, conv2x2(X, wk, bias, h, w + 1));
    m = fmaxf(m, conv2x2(X, wk, bias, h + 1, w));
    m = fmaxf(m, conv2x2(X, wk, bias, h + 1, w + 1));
    y1[(size_t)b * 9800 + idx] = fmaxf(m, 0.f);
}

// branch b stage 2: conv(w6, s2)+b6 -> relu -> maxpool (1,6) s6 -> cat[:, 2450:]
__global__ void k_b2(const float* __restrict__ y1,
                     const float* __restrict__ w6,
                     const float* __restrict__ b6,
                     float* __restrict__ cat)
{
    int t = blockIdx.x * blockDim.x + threadIdx.x;
    int b = blockIdx.y;
    if (t >= 32 * 408) return;
    int c = t / 408, j = t - c * 408;
    float w0 = w6[c * 4 + 0], w1v = w6[c * 4 + 1];
    float w2 = w6[c * 4 + 2], w3 = w6[c * 4 + 3];
    float bias = b6[c];
    const float* Y0 = y1 + (size_t)b * 9800;
    const float* Y1 = Y0 + 4900;
    float m = -3.4e38f;
#pragma unroll
    for (int tt = 0; tt < 6; tt++) {
        int wp = 6 * j + tt;  // <= 2447 < 2450
        float s = bias + Y0[2 * wp] * w0 + Y0[2 * wp + 1] * w1v
                       + Y1[2 * wp] * w2 + Y1[2 * wp + 1] * w3;
        m = fmaxf(m, s);
    }
    cat[(size_t)b * 15506 + 2450 + t] = fmaxf(m, 0.f);
}

// final: out(64,2) = z2(64,2000) @ Wf3(2000,2) + bf3 (exact fp32 block-reduce)
__global__ void k_final(const float* __restrict__ z2,
                        const float* __restrict__ Wf3,
                        const float* __restrict__ bf3,
                        float* __restrict__ out)
{
    int b = blockIdx.x >> 1;
    int c = blockIdx.x & 1;
    const float* Z = z2 + b * 2000;
    float s = 0.f;
    for (int k = threadIdx.x; k < 2000; k += 128)
        s += Z[k] * Wf3[2 * k + c];
    __shared__ float red[128];
    red[threadIdx.x] = s;
    __syncthreads();
    for (int d = 64; d > 0; d >>= 1) {
        if (threadIdx.x < d) red[threadIdx.x] += red[threadIdx.x + d];
        __syncthreads();
    }
    if (threadIdx.x == 0) out[b * 2 + c] = red[0] + bf3[c];
}

// ---------------------------------------------------------------------------
// launch
// ---------------------------------------------------------------------------
extern "C" void kernel_launch(void* const* d_in, const int* in_sizes, int n_in,
                              void* d_out, int out_size)
{
    const float* x1  = (const float*)d_in[0];
    const float* x2  = (const float*)d_in[1];
    const float* w1  = (const float*)d_in[2];
    const float* b1  = (const float*)d_in[3];
    const float* Wa  = (const float*)d_in[4];
    const float* ba  = (const float*)d_in[5];
    const float* Wb  = (const float*)d_in[6];
    const float* bb  = (const float*)d_in[7];
    const float* Wc  = (const float*)d_in[8];
    const float* bc  = (const float*)d_in[9];
    const float* lw  = (const float*)d_in[10];
    const float* lb  = (const float*)d_in[11];
    const float* w5  = (const float*)d_in[12];
    const float* b5  = (const float*)d_in[13];
    const float* w6  = (const float*)d_in[14];
    const float* b6  = (const float*)d_in[15];
    const float* Wf1 = (const float*)d_in[16];
    const float* bf1 = (const float*)d_in[17];
    const float* Wf2 = (const float*)d_in[18];
    const float* bf2 = (const float*)d_in[19];
    const float* Wf3 = (const float*)d_in[20];
    const float* bf3 = (const float*)d_in[21];
    float* out = (float*)d_out;

    float* S = nullptr;
    cudaGetSymbolAddress((void**)&S, g_scratch);
    float* A4   = S + OFF_A4;
    float* h1   = S + OFF_H1;
    float* h2   = S + OFF_H2;
    float* dynw = S + OFF_DYNW;
    float* y1   = S + OFF_Y1;
    float* cat  = S + OFF_CAT;
    float* z1   = S + OFF_Z1;
    float* z2   = S + OFF_Z2;
    float* part = S + OFF_PART;

    // branch a front
    k_a_front<<<dim3(20, 64), 256>>>(x1, w1, b1, A4);

    // h1 = relu(A4 @ Wa + ba)   [K=4899, N=1000] split-tf32, splitK=16
    gemm64<true><<<dim3(8, 16), 256>>>(A4, Wa, part, 4899, 1000, 16);
    epilogue<<<(64 * 1000 + 255) / 256, 256>>>(part, ba, h1, 1000, 16, 1);

    // h2 = relu(h1 @ Wb + bb)   [K=1000, N=500] split-tf32, splitK=16
    gemm64<true><<<dim3(4, 16), 256>>>(h1, Wb, part, 1000, 500, 16);
    epilogue<<<(64 * 500 + 255) / 256, 256>>>(part, bb, h2, 500, 16, 1);

    // dynamic weights + per-sample conv -> cat[:, 0:2450]
    k_dynw<<<3, 256>>>(h2, Wc, bc, lw, dynw);
    k_dynconv<<<dim3(10, 64), 256>>>(x1, dynw, lb, cat);

    // branch b -> cat[:, 2450:]
    k_b1<<<dim3(39, 64), 256>>>(x2, w5, b5, y1);
    k_b2<<<dim3(51, 64), 256>>>(y1, w6, b6, cat);

    // z1 = relu(cat @ Wf1 + bf1) [K=15506, N=8000] single tf32, splitK=2
    gemm64<false><<<dim3(63, 2), 256>>>(cat, Wf1, part, 15506, 8000, 2);
    epilogue<<<(64 * 8000 + 255) / 256, 256>>>(part, bf1, z1, 8000, 2, 1);

    // z2 = relu(z1 @ Wf2 + bf2)  [K=8000, N=2000] split-tf32, splitK=8
    gemm64<true><<<dim3(16, 8), 256>>>(z1, Wf2, part, 8000, 2000, 8);
    epilogue<<<(64 * 2000 + 255) / 256, 256>>>(part, bf2, z2, 2000, 8, 1);

    // out = z2 @ Wf3 + bf3
    k_final<<<128, 128>>>(z2, Wf3, bf3, out);
}

// round 7
// speedup vs baseline: 1.0102x; 1.0002x over previous
#include <cuda_runtime.h>
#include <cuda_bf16.h>
#include <cstdint>

// ---------------------------------------------------------------------------
// Scratch (single static device buffer, offsets in floats)
// ---------------------------------------------------------------------------
#define OFF_A4    0              // 64*4899  = 313536
#define OFF_H1    313536         // 64*1000  = 64000
#define OFF_H2    377536         // 64*500   = 32000
#define OFF_DYNW  409536         // 64*9     = 576
#define OFF_Y1    410112         // 64*2*4900= 627200
#define OFF_CAT   1037312        // 64*15506 = 992384
#define OFF_Z1    2029696        // 64*8000  = 512000
#define OFF_Z2    2541696        // 64*2000  = 128000
#define OFF_PART  2669696        // up to 16*64*1000 / 2*64*8000 / 8*64*2000 = 1.024M
#define SCRATCH_FLOATS 3800000

__device__ float g_scratch[SCRATCH_FLOATS];

// ---------------------------------------------------------------------------
// TF32 helpers
// ---------------------------------------------------------------------------
__device__ __forceinline__ uint32_t f2tf(float x) {
    uint32_t r;
    asm("cvt.rna.tf32.f32 %0, %1;" : "=r"(r) : "f"(x));
    return r;
}

__device__ __forceinline__ void mma_tf32(float* c, const uint32_t* a,
                                         uint32_t b0, uint32_t b1) {
    asm("mma.sync.aligned.m16n8k8.row.col.f32.tf32.tf32.f32 "
        "{%0,%1,%2,%3},{%4,%5,%6,%7},{%8,%9},{%0,%1,%2,%3};"
        : "+f"(c[0]), "+f"(c[1]), "+f"(c[2]), "+f"(c[3])
        : "r"(a[0]), "r"(a[1]), "r"(a[2]), "r"(a[3]), "r"(b0), "r"(b1));
}

// ---------------------------------------------------------------------------
// GEMM: C_part[s] = A(64 x K) @ B(K x N), row-major both.
// 256 threads = 8 warps. Warp computes all 64 rows x 16 cols (2 n8-tiles).
// CTA covers 128 cols. gridDim.y = splitK; each split writes its own
// disjoint partial slab (deterministic, no atomics).
// SPLIT=true: 3-term split-TF32 (near-fp32 accuracy).
// ---------------------------------------------------------------------------
template <bool SPLIT>
__global__ __launch_bounds__(256) void gemm64(
    const float* __restrict__ A, const float* __restrict__ B,
    float* __restrict__ part, int K, int N, int splitk)
{
    const int warp = threadIdx.x >> 5;
    const int lane = threadIdx.x & 31;
    const int grp  = lane >> 2;      // 0..7
    const int qid  = lane & 3;       // 0..3
    const int nb   = blockIdx.x * 128 + warp * 16;
    const int s    = blockIdx.y;
    const int kchunk = (K + splitk - 1) / splitk;
    const int k0 = s * kchunk;
    const int k1 = min(K, k0 + kchunk);

    float acc[4][2][4];
#pragma unroll
    for (int t = 0; t < 4; t++)
#pragma unroll
        for (int j = 0; j < 2; j++)
#pragma unroll
            for (int i = 0; i < 4; i++) acc[t][j][i] = 0.f;

    const int n0 = nb + grp;
    const int n1 = nb + 8 + grp;
    const bool pn0 = n0 < N;
    const bool pn1 = n1 < N;

    for (int kk = k0; kk < k1; kk += 8) {
        const int c0 = kk + qid;
        const int c1 = c0 + 4;
        const bool p0 = c0 < k1;
        const bool p1 = c1 < k1;

        // ---- B fragment loads (streaming; 100% sector efficiency) ----
        float fb[2][2];
        fb[0][0] = (p0 && pn0) ? B[(size_t)c0 * N + n0] : 0.f;
        fb[0][1] = (p1 && pn0) ? B[(size_t)c1 * N + n0] : 0.f;
        fb[1][0] = (p0 && pn1) ? B[(size_t)c0 * N + n1] : 0.f;
        fb[1][1] = (p1 && pn1) ? B[(size_t)c1 * N + n1] : 0.f;

        // ---- A fragment loads (L2-resident activations) ----
        float fa[4][4];
#pragma unroll
        for (int t = 0; t < 4; t++) {
            const float* Ar = A + (size_t)(t * 16 + grp) * K;
            fa[t][0] = p0 ? Ar[c0]         : 0.f;
            fa[t][1] = p0 ? Ar[8 * (size_t)K + c0] : 0.f;
            fa[t][2] = p1 ? Ar[c1]         : 0.f;
            fa[t][3] = p1 ? Ar[8 * (size_t)K + c1] : 0.f;
        }

        uint32_t bhi[2][2], ahi[4][4];
#pragma unroll
        for (int j = 0; j < 2; j++) {
            bhi[j][0] = f2tf(fb[j][0]);
            bhi[j][1] = f2tf(fb[j][1]);
        }
#pragma unroll
        for (int t = 0; t < 4; t++)
#pragma unroll
            for (int i = 0; i < 4; i++) ahi[t][i] = f2tf(fa[t][i]);

        if (SPLIT) {
            uint32_t blo[2][2], alo[4][4];
#pragma unroll
            for (int j = 0; j < 2; j++)
#pragma unroll
                for (int i = 0; i < 2; i++)
                    blo[j][i] = f2tf(fb[j][i] - __uint_as_float(bhi[j][i]));
#pragma unroll
            for (int t = 0; t < 4; t++)
#pragma unroll
                for (int i = 0; i < 4; i++)
                    alo[t][i] = f2tf(fa[t][i] - __uint_as_float(ahi[t][i]));
#pragma unroll
            for (int t = 0; t < 4; t++) {
#pragma unroll
                for (int j = 0; j < 2; j++) {
                    mma_tf32(acc[t][j], alo[t], bhi[j][0], bhi[j][1]);
                    mma_tf32(acc[t][j], ahi[t], blo[j][0], blo[j][1]);
                    mma_tf32(acc[t][j], ahi[t], bhi[j][0], bhi[j][1]);
                }
            }
        } else {
#pragma unroll
            for (int t = 0; t < 4; t++)
#pragma unroll
                for (int j = 0; j < 2; j++)
                    mma_tf32(acc[t][j], ahi[t], bhi[j][0], bhi[j][1]);
        }
    }

    // ---- store partials ----
#pragma unroll
    for (int t = 0; t < 4; t++) {
#pragma unroll
        for (int j = 0; j < 2; j++) {
            const int col = nb + 8 * j + 2 * qid;
            const int row = t * 16 + grp;
            float* p = part + (size_t)(s * 64 + row) * N + col;
            if (col < N) {
                p[0]               = acc[t][j][0];
                p[(size_t)8 * N]   = acc[t][j][2];
            }
            if (col + 1 < N) {
                p[1]                 = acc[t][j][1];
                p[(size_t)8 * N + 1] = acc[t][j][3];
            }
        }
    }
}

// Reduce splitK partials + bias (+ReLU)
__global__ void epilogue(const float* __restrict__ part,
                         const float* __restrict__ bias,
                         float* __restrict__ out, int N, int splitk, int do_relu)
{
    int idx = blockIdx.x * blockDim.x + threadIdx.x;
    if (idx >= 64 * N) return;
    int row = idx / N, col = idx - row * N;
    float s = bias[col];
    for (int p = 0; p < splitk; p++)
        s += part[(size_t)(p * 64 + row) * N + col];
    out[idx] = do_relu ? fmaxf(s, 0.f) : s;
}

// ---------------------------------------------------------------------------
// Elementwise / small kernels
// ---------------------------------------------------------------------------

// 3x3 conv at (h, wpos) over a 2x4900 image with pad 1
__device__ __forceinline__ float conv3(const float* X, const float* w,
                                       float bias, int h, int wpos)
{
    float s = bias;
#pragma unroll
    for (int dh = 0; dh < 3; dh++) {
        int ih = h + dh - 1;
        if (ih < 0 || ih > 1) continue;
        const float* R = X + ih * 4900;
#pragma unroll
        for (int dw = 0; dw < 3; dw++) {
            int iw = wpos + dw - 1;
            if (iw >= 0 && iw < 4900) s += R[iw] * w[dh * 3 + dw];
        }
    }
    return s;
}

// branch a front: conv(w1,pad1)+b1 -> relu -> maxpool 2x2 s1 -> A4 (64,4899)
__global__ void k_a_front(const float* __restrict__ x1,
                          const float* __restrict__ w1,
                          const float* __restrict__ b1,
                          float* __restrict__ A4)
{
    int j = blockIdx.x * blockDim.x + threadIdx.x;
    int b = blockIdx.y;
    if (j >= 4899) return;
    const float* X = x1 + (size_t)b * 9800;
    float w[9];
#pragma unroll
    for (int i = 0; i < 9; i++) w[i] = w1[i];
    float bias = b1[0];
    float m = conv3(X, w, bias, 0, j);
    m = fmaxf(m, conv3(X, w, bias, 0, j + 1));
    m = fmaxf(m, conv3(X, w, bias, 1, j));
    m = fmaxf(m, conv3(X, w, bias, 1, j + 1));
    A4[(size_t)b * 4899 + j] = fmaxf(m, 0.f);
}

// a3 = h2 @ Wc + bc ; dynw = lw * a3   (64 x 9 outputs, K=500)
__global__ void k_dynw(const float* __restrict__ h2,
                       const float* __restrict__ Wc,
                       const float* __restrict__ bc,
                       const float* __restrict__ lw,
                       float* __restrict__ dynw)
{
    int t = blockIdx.x * blockDim.x + threadIdx.x;
    if (t >= 64 * 9) return;
    int b = t / 9, i = t - b * 9;
    const float* H = h2 + b * 500;
    float s = bc[i];
    for (int k = 0; k < 500; k++) s += H[k] * Wc[k * 9 + i];
    dynw[t] = s * lw[t];
}

// per-sample dynamic 3x3 conv + lb -> relu -> maxpool 2x2 s2 -> cat[:, 0:2450]
__global__ void k_dynconv(const float* __restrict__ x1,
                          const float* __restrict__ dynw,
                          const float* __restrict__ lb,
                          float* __restrict__ cat)
{
    int j = blockIdx.x * blockDim.x + threadIdx.x;
    int b = blockIdx.y;
    if (j >= 2450) return;
    const float* X = x1 + (size_t)b * 9800;
    float w[9];
#pragma unroll
    for (int i = 0; i < 9; i++) w[i] = dynw[b * 9 + i];
    float bias = lb[b];
    float m = conv3(X, w, bias, 0, 2 * j);
    m = fmaxf(m, conv3(X, w, bias, 0, 2 * j + 1));
    m = fmaxf(m, conv3(X, w, bias, 1, 2 * j));
    m = fmaxf(m, conv3(X, w, bias, 1, 2 * j + 1));
    cat[(size_t)b * 15506 + j] = fmaxf(m, 0.f);
}

// 2x2 conv at (hh in 0..2, ww in 0..4900) over 2x4900 image, pad 1
__device__ __forceinline__ float conv2x2(const float* X, const float* w,
                                         float bias, int hh, int ww)
{
    float s = bias;
#pragma unroll
    for (int dh = 0; dh < 2; dh++) {
        int ih = hh - 1 + dh;
        if (ih < 0 || ih > 1) continue;
        const float* R = X + ih * 4900;
#pragma unroll
        for (int dw = 0; dw < 2; dw++) {
            int iw = ww - 1 + dw;
            if (iw >= 0 && iw < 4900) s += R[iw] * w[dh * 2 + dw];
        }
    }
    return s;
}

// branch b stage 1: conv(w5,pad1)+b5 -> relu -> maxpool 2x2 s1 -> y1 (64,2,4900)
__global__ void k_b1(const float* __restrict__ x2,
                     const float* __restrict__ w5,
                     const float* __restrict__ b5,
                     float* __restrict__ y1)
{
    int idx = blockIdx.x * blockDim.x + threadIdx.x;
    int b = blockIdx.y;
    if (idx >= 9800) return;
    int h = idx / 4900, w = idx - h * 4900;
    const float* X = x2 + (size_t)b * 9800;
    float wk[4];
#pragma unroll
    for (int i = 0; i < 4; i++) wk[i] = w5[i];
    float bias = b5[0];
    float m = conv2x2(X, wk, bias, h, w);
    m = fmaxf(m, conv2x2(X, wk, bias, h, w + 1));
    m = fmaxf(m, conv2x2(X, wk, bias, h + 1, w));
    m = fmaxf(m, conv2x2(X, wk, bias, h + 1, w + 1));
    y1[(size_t)b * 9800 + idx] = fmaxf(m, 0.f);
}

// branch b stage 2: conv(w6, s2)+b6 -> relu -> maxpool (1,6) s6 -> cat[:, 2450:]
__global__ void k_b2(const float* __restrict__ y1,
                     const float* __restrict__ w6,
                     const float* __restrict__ b6,
                     float* __restrict__ cat)
{
    int t = blockIdx.x * blockDim.x + threadIdx.x;
    int b = blockIdx.y;
    if (t >= 32 * 408) return;
    int c = t / 408, j = t - c * 408;
    float w0 = w6[c * 4 + 0], w1v = w6[c * 4 + 1];
    float w2 = w6[c * 4 + 2], w3 = w6[c * 4 + 3];
    float bias = b6[c];
    const float* Y0 = y1 + (size_t)b * 9800;
    const float* Y1 = Y0 + 4900;
    float m = -3.4e38f;
#pragma unroll
    for (int tt = 0; tt < 6; tt++) {
        int wp = 6 * j + tt;  // <= 2447 < 2450
        float s = bias + Y0[2 * wp] * w0 + Y0[2 * wp + 1] * w1v
                       + Y1[2 * wp] * w2 + Y1[2 * wp + 1] * w3;
        m = fmaxf(m, s);
    }
    cat[(size_t)b * 15506 + 2450 + t] = fmaxf(m, 0.f);
}

// final: out(64,2) = z2(64,2000) @ Wf3(2000,2) + bf3 (exact fp32 block-reduce)
__global__ void k_final(const float* __restrict__ z2,
                        const float* __restrict__ Wf3,
                        const float* __restrict__ bf3,
                        float* __restrict__ out)
{
    int b = blockIdx.x >> 1;
    int c = blockIdx.x & 1;
    const float* Z = z2 + b * 2000;
    float s = 0.f;
    for (int k = threadIdx.x; k < 2000; k += 128)
        s += Z[k] * Wf3[2 * k + c];
    __shared__ float red[128];
    red[threadIdx.x] = s;
    __syncthreads();
    for (int d = 64; d > 0; d >>= 1) {
        if (threadIdx.x < d) red[threadIdx.x] += red[threadIdx.x + d];
        __syncthreads();
    }
    if (threadIdx.x == 0) out[b * 2 + c] = red[0] + bf3[c];
}

// ---------------------------------------------------------------------------
// launch
// ---------------------------------------------------------------------------
extern "C" void kernel_launch(void* const* d_in, const int* in_sizes, int n_in,
                              void* d_out, int out_size)
{
    const float* x1  = (const float*)d_in[0];
    const float* x2  = (const float*)d_in[1];
    const float* w1  = (const float*)d_in[2];
    const float* b1  = (const float*)d_in[3];
    const float* Wa  = (const float*)d_in[4];
    const float* ba  = (const float*)d_in[5];
    const float* Wb  = (const float*)d_in[6];
    const float* bb  = (const float*)d_in[7];
    const float* Wc  = (const float*)d_in[8];
    const float* bc  = (const float*)d_in[9];
    const float* lw  = (const float*)d_in[10];
    const float* lb  = (const float*)d_in[11];
    const float* w5  = (const float*)d_in[12];
    const float* b5  = (const float*)d_in[13];
    const float* w6  = (const float*)d_in[14];
    const float* b6  = (const float*)d_in[15];
    const float* Wf1 = (const float*)d_in[16];
    const float* bf1 = (const float*)d_in[17];
    const float* Wf2 = (const float*)d_in[18];
    const float* bf2 = (const float*)d_in[19];
    const float* Wf3 = (const float*)d_in[20];
    const float* bf3 = (const float*)d_in[21];
    float* out = (float*)d_out;

    float* S = nullptr;
    cudaGetSymbolAddress((void**)&S, g_scratch);
    float* A4   = S + OFF_A4;
    float* h1   = S + OFF_H1;
    float* h2   = S + OFF_H2;
    float* dynw = S + OFF_DYNW;
    float* y1   = S + OFF_Y1;
    float* cat  = S + OFF_CAT;
    float* z1   = S + OFF_Z1;
    float* z2   = S + OFF_Z2;
    float* part = S + OFF_PART;

    // branch a front
    k_a_front<<<dim3(20, 64), 256>>>(x1, w1, b1, A4);

    // h1 = relu(A4 @ Wa + ba)   [K=4899, N=1000] split-tf32, splitK=16
    gemm64<true><<<dim3(8, 16), 256>>>(A4, Wa, part, 4899, 1000, 16);
    epilogue<<<(64 * 1000 + 255) / 256, 256>>>(part, ba, h1, 1000, 16, 1);

    // h2 = relu(h1 @ Wb + bb)   [K=1000, N=500] split-tf32, splitK=16
    gemm64<true><<<dim3(4, 16), 256>>>(h1, Wb, part, 1000, 500, 16);
    epilogue<<<(64 * 500 + 255) / 256, 256>>>(part, bb, h2, 500, 16, 1);

    // dynamic weights + per-sample conv -> cat[:, 0:2450]
    k_dynw<<<3, 256>>>(h2, Wc, bc, lw, dynw);
    k_dynconv<<<dim3(10, 64), 256>>>(x1, dynw, lb, cat);

    // branch b -> cat[:, 2450:]
    k_b1<<<dim3(39, 64), 256>>>(x2, w5, b5, y1);
    k_b2<<<dim3(51, 64), 256>>>(y1, w6, b6, cat);

    // z1 = relu(cat @ Wf1 + bf1) [K=15506, N=8000] single tf32, splitK=2
    gemm64<false><<<dim3(63, 2), 256>>>(cat, Wf1, part, 15506, 8000, 2);
    epilogue<<<(64 * 8000 + 255) / 256, 256>>>(part, bf1, z1, 8000, 2, 1);

    // z2 = relu(z1 @ Wf2 + bf2)  [K=8000, N=2000] split-tf32, splitK=8
    gemm64<true><<<dim3(16, 8), 256>>>(z1, Wf2, part, 8000, 2000, 8);
    epilogue<<<(64 * 2000 + 255) / 256, 256>>>(part, bf2, z2, 2000, 8, 1);

    // out = z2 @ Wf3 + bf3
    k_final<<<128, 128>>>(z2, Wf3, bf3, out);
}

// round 8
// speedup vs baseline: 1.0698x; 1.0590x over previous
#include <cuda_runtime.h>
#include <cuda_bf16.h>
#include <cstdint>

// ---------------------------------------------------------------------------
// Scratch (single static device buffer, offsets in floats)
// ---------------------------------------------------------------------------
#define OFF_A4    0              // 64*4899  = 313536
#define OFF_H1    313536         // 64*1000  = 64000
#define OFF_H2    377536         // 64*500   = 32000
#define OFF_DYNW  409536         // 64*9     = 576
#define OFF_Y1    410112         // 64*2*4900= 627200
#define OFF_CAT   1037312        // 64*15506 = 992384
#define OFF_Z1    2029696        // 64*8000  = 512000
#define OFF_Z2    2541696        // 64*2000  = 128000
#define OFF_PART  2669696        // up to 16*64*1000 / 2*64*8000 / 8*64*2000 = 1.024M
#define SCRATCH_FLOATS 3800000

__device__ float g_scratch[SCRATCH_FLOATS];

// ---------------------------------------------------------------------------
// TF32 helpers
// ---------------------------------------------------------------------------
__device__ __forceinline__ uint32_t f2tf(float x) {
    uint32_t r;
    asm("cvt.rna.tf32.f32 %0, %1;" : "=r"(r) : "f"(x));
    return r;
}

__device__ __forceinline__ void mma_tf32(float* c, const uint32_t* a,
                                         uint32_t b0, uint32_t b1) {
    asm("mma.sync.aligned.m16n8k8.row.col.f32.tf32.tf32.f32 "
        "{%0,%1,%2,%3},{%4,%5,%6,%7},{%8,%9},{%0,%1,%2,%3};"
        : "+f"(c[0]), "+f"(c[1]), "+f"(c[2]), "+f"(c[3])
        : "r"(a[0]), "r"(a[1]), "r"(a[2]), "r"(a[3]), "r"(b0), "r"(b1));
}

// ---------------------------------------------------------------------------
// GEMM: C_part[s] = A(64 x K) @ B(K x N), row-major both.
// 256 threads = 8 warps. Warp computes all 64 rows x 16 cols (2 n8-tiles).
// CTA covers 128 cols. gridDim.y = splitK; each split writes its own
// disjoint partial slab (deterministic, no atomics).
// SPLIT=true: 3-term split-TF32 (near-fp32 accuracy).
// ---------------------------------------------------------------------------
template <bool SPLIT>
__global__ __launch_bounds__(256) void gemm64(
    const float* __restrict__ A, const float* __restrict__ B,
    float* __restrict__ part, int K, int N, int splitk)
{
    const int warp = threadIdx.x >> 5;
    const int lane = threadIdx.x & 31;
    const int grp  = lane >> 2;      // 0..7
    const int qid  = lane & 3;       // 0..3
    const int nb   = blockIdx.x * 128 + warp * 16;
    const int s    = blockIdx.y;
    const int kchunk = (K + splitk - 1) / splitk;
    const int k0 = s * kchunk;
    const int k1 = min(K, k0 + kchunk);

    float acc[4][2][4];
#pragma unroll
    for (int t = 0; t < 4; t++)
#pragma unroll
        for (int j = 0; j < 2; j++)
#pragma unroll
            for (int i = 0; i < 4; i++) acc[t][j][i] = 0.f;

    const int n0 = nb + grp;
    const int n1 = nb + 8 + grp;
    const bool pn0 = n0 < N;
    const bool pn1 = n1 < N;

    for (int kk = k0; kk < k1; kk += 8) {
        const int c0 = kk + qid;
        const int c1 = c0 + 4;
        const bool p0 = c0 < k1;
        const bool p1 = c1 < k1;

        // ---- B fragment loads (streaming; 100% sector efficiency) ----
        float fb[2][2];
        fb[0][0] = (p0 && pn0) ? B[(size_t)c0 * N + n0] : 0.f;
        fb[0][1] = (p1 && pn0) ? B[(size_t)c1 * N + n0] : 0.f;
        fb[1][0] = (p0 && pn1) ? B[(size_t)c0 * N + n1] : 0.f;
        fb[1][1] = (p1 && pn1) ? B[(size_t)c1 * N + n1] : 0.f;

        // ---- A fragment loads (L2-resident activations) ----
        float fa[4][4];
#pragma unroll
        for (int t = 0; t < 4; t++) {
            const float* Ar = A + (size_t)(t * 16 + grp) * K;
            fa[t][0] = p0 ? Ar[c0]         : 0.f;
            fa[t][1] = p0 ? Ar[8 * (size_t)K + c0] : 0.f;
            fa[t][2] = p1 ? Ar[c1]         : 0.f;
            fa[t][3] = p1 ? Ar[8 * (size_t)K + c1] : 0.f;
        }

        uint32_t bhi[2][2], ahi[4][4];
#pragma unroll
        for (int j = 0; j < 2; j++) {
            bhi[j][0] = f2tf(fb[j][0]);
            bhi[j][1] = f2tf(fb[j][1]);
        }
#pragma unroll
        for (int t = 0; t < 4; t++)
#pragma unroll
            for (int i = 0; i < 4; i++) ahi[t][i] = f2tf(fa[t][i]);

        if (SPLIT) {
            uint32_t blo[2][2], alo[4][4];
#pragma unroll
            for (int j = 0; j < 2; j++)
#pragma unroll
                for (int i = 0; i < 2; i++)
                    blo[j][i] = f2tf(fb[j][i] - __uint_as_float(bhi[j][i]));
#pragma unroll
            for (int t = 0; t < 4; t++)
#pragma unroll
                for (int i = 0; i < 4; i++)
                    alo[t][i] = f2tf(fa[t][i] - __uint_as_float(ahi[t][i]));
#pragma unroll
            for (int t = 0; t < 4; t++) {
#pragma unroll
                for (int j = 0; j < 2; j++) {
                    mma_tf32(acc[t][j], alo[t], bhi[j][0], bhi[j][1]);
                    mma_tf32(acc[t][j], ahi[t], blo[j][0], blo[j][1]);
                    mma_tf32(acc[t][j], ahi[t], bhi[j][0], bhi[j][1]);
                }
            }
        } else {
#pragma unroll
            for (int t = 0; t < 4; t++)
#pragma unroll
                for (int j = 0; j < 2; j++)
                    mma_tf32(acc[t][j], ahi[t], bhi[j][0], bhi[j][1]);
        }
    }

    // ---- store partials ----
#pragma unroll
    for (int t = 0; t < 4; t++) {
#pragma unroll
        for (int j = 0; j < 2; j++) {
            const int col = nb + 8 * j + 2 * qid;
            const int row = t * 16 + grp;
            float* p = part + (size_t)(s * 64 + row) * N + col;
            if (col < N) {
                p[0]               = acc[t][j][0];
                p[(size_t)8 * N]   = acc[t][j][2];
            }
            if (col + 1 < N) {
                p[1]                 = acc[t][j][1];
                p[(size_t)8 * N + 1] = acc[t][j][3];
            }
        }
    }
}

// Reduce splitK partials + bias (+ReLU)
__global__ void epilogue(const float* __restrict__ part,
                         const float* __restrict__ bias,
                         float* __restrict__ out, int N, int splitk, int do_relu)
{
    int idx = blockIdx.x * blockDim.x + threadIdx.x;
    if (idx >= 64 * N) return;
    int row = idx / N, col = idx - row * N;
    float s = bias[col];
    for (int p = 0; p < splitk; p++)
        s += part[(size_t)(p * 64 + row) * N + col];
    out[idx] = do_relu ? fmaxf(s, 0.f) : s;
}

// ---------------------------------------------------------------------------
// Elementwise / small kernels
// ---------------------------------------------------------------------------

// 3x3 conv at (h, wpos) over a 2x4900 image with pad 1
__device__ __forceinline__ float conv3(const float* X, const float* w,
                                       float bias, int h, int wpos)
{
    float s = bias;
#pragma unroll
    for (int dh = 0; dh < 3; dh++) {
        int ih = h + dh - 1;
        if (ih < 0 || ih > 1) continue;
        const float* R = X + ih * 4900;
#pragma unroll
        for (int dw = 0; dw < 3; dw++) {
            int iw = wpos + dw - 1;
            if (iw >= 0 && iw < 4900) s += R[iw] * w[dh * 3 + dw];
        }
    }
    return s;
}

// branch a front: conv(w1,pad1)+b1 -> relu -> maxpool 2x2 s1 -> A4 (64,4899)
__global__ void k_a_front(const float* __restrict__ x1,
                          const float* __restrict__ w1,
                          const float* __restrict__ b1,
                          float* __restrict__ A4)
{
    int j = blockIdx.x * blockDim.x + threadIdx.x;
    int b = blockIdx.y;
    if (j >= 4899) return;
    const float* X = x1 + (size_t)b * 9800;
    float w[9];
#pragma unroll
    for (int i = 0; i < 9; i++) w[i] = w1[i];
    float bias = b1[0];
    float m = conv3(X, w, bias, 0, j);
    m = fmaxf(m, conv3(X, w, bias, 0, j + 1));
    m = fmaxf(m, conv3(X, w, bias, 1, j));
    m = fmaxf(m, conv3(X, w, bias, 1, j + 1));
    A4[(size_t)b * 4899 + j] = fmaxf(m, 0.f);
}

// a3 = h2 @ Wc + bc ; dynw = lw * a3   (64 x 9 outputs, K=500)
__global__ void k_dynw(const float* __restrict__ h2,
                       const float* __restrict__ Wc,
                       const float* __restrict__ bc,
                       const float* __restrict__ lw,
                       float* __restrict__ dynw)
{
    int t = blockIdx.x * blockDim.x + threadIdx.x;
    if (t >= 64 * 9) return;
    int b = t / 9, i = t - b * 9;
    const float* H = h2 + b * 500;
    float s = bc[i];
    for (int k = 0; k < 500; k++) s += H[k] * Wc[k * 9 + i];
    dynw[t] = s * lw[t];
}

// per-sample dynamic 3x3 conv + lb -> relu -> maxpool 2x2 s2 -> cat[:, 0:2450]
__global__ void k_dynconv(const float* __restrict__ x1,
                          const float* __restrict__ dynw,
                          const float* __restrict__ lb,
                          float* __restrict__ cat)
{
    int j = blockIdx.x * blockDim.x + threadIdx.x;
    int b = blockIdx.y;
    if (j >= 2450) return;
    const float* X = x1 + (size_t)b * 9800;
    float w[9];
#pragma unroll
    for (int i = 0; i < 9; i++) w[i] = dynw[b * 9 + i];
    float bias = lb[b];
    float m = conv3(X, w, bias, 0, 2 * j);
    m = fmaxf(m, conv3(X, w, bias, 0, 2 * j + 1));
    m = fmaxf(m, conv3(X, w, bias, 1, 2 * j));
    m = fmaxf(m, conv3(X, w, bias, 1, 2 * j + 1));
    cat[(size_t)b * 15506 + j] = fmaxf(m, 0.f);
}

// 2x2 conv at (hh in 0..2, ww in 0..4900) over 2x4900 image, pad 1
__device__ __forceinline__ float conv2x2(const float* X, const float* w,
                                         float bias, int hh, int ww)
{
    float s = bias;
#pragma unroll
    for (int dh = 0; dh < 2; dh++) {
        int ih = hh - 1 + dh;
        if (ih < 0 || ih > 1) continue;
        const float* R = X + ih * 4900;
#pragma unroll
        for (int dw = 0; dw < 2; dw++) {
            int iw = ww - 1 + dw;
            if (iw >= 0 && iw < 4900) s += R[iw] * w[dh * 2 + dw];
        }
    }
    return s;
}

// branch b stage 1: conv(w5,pad1)+b5 -> relu -> maxpool 2x2 s1 -> y1 (64,2,4900)
__global__ void k_b1(const float* __restrict__ x2,
                     const float* __restrict__ w5,
                     const float* __restrict__ b5,
                     float* __restrict__ y1)
{
    int idx = blockIdx.x * blockDim.x + threadIdx.x;
    int b = blockIdx.y;
    if (idx >= 9800) return;
    int h = idx / 4900, w = idx - h * 4900;
    const float* X = x2 + (size_t)b * 9800;
    float wk[4];
#pragma unroll
    for (int i = 0; i < 4; i++) wk[i] = w5[i];
    float bias = b5[0];
    float m = conv2x2(X, wk, bias, h, w);
    m = fmaxf(m, conv2x2(X, wk, bias, h, w + 1));
    m = fmaxf(m, conv2x2(X, wk, bias, h + 1, w));
    m = fmaxf(m, conv2x2(X, wk, bias, h + 1, w + 1));
    y1[(size_t)b * 9800 + idx] = fmaxf(m, 0.f);
}

// branch b stage 2: conv(w6, s2)+b6 -> relu -> maxpool (1,6) s6 -> cat[:, 2450:]
__global__ void k_b2(const float* __restrict__ y1,
                     const float* __restrict__ w6,
                     const float* __restrict__ b6,
                     float* __restrict__ cat)
{
    int t = blockIdx.x * blockDim.x + threadIdx.x;
    int b = blockIdx.y;
    if (t >= 32 * 408) return;
    int c = t / 408, j = t - c * 408;
    float w0 = w6[c * 4 + 0], w1v = w6[c * 4 + 1];
    float w2 = w6[c * 4 + 2], w3 = w6[c * 4 + 3];
    float bias = b6[c];
    const float* Y0 = y1 + (size_t)b * 9800;
    const float* Y1 = Y0 + 4900;
    float m = -3.4e38f;
#pragma unroll
    for (int tt = 0; tt < 6; tt++) {
        int wp = 6 * j + tt;  // <= 2447 < 2450
        float s = bias + Y0[2 * wp] * w0 + Y0[2 * wp + 1] * w1v
                       + Y1[2 * wp] * w2 + Y1[2 * wp + 1] * w3;
        m = fmaxf(m, s);
    }
    cat[(size_t)b * 15506 + 2450 + t] = fmaxf(m, 0.f);
}

// final: out(64,2) = z2(64,2000) @ Wf3(2000,2) + bf3 (exact fp32 block-reduce)
__global__ void k_final(const float* __restrict__ z2,
                        const float* __restrict__ Wf3,
                        const float* __restrict__ bf3,
                        float* __restrict__ out)
{
    int b = blockIdx.x >> 1;
    int c = blockIdx.x & 1;
    const float* Z = z2 + b * 2000;
    float s = 0.f;
    for (int k = threadIdx.x; k < 2000; k += 128)
        s += Z[k] * Wf3[2 * k + c];
    __shared__ float red[128];
    red[threadIdx.x] = s;
    __syncthreads();
    for (int d = 64; d > 0; d >>= 1) {
        if (threadIdx.x < d) red[threadIdx.x] += red[threadIdx.x + d];
        __syncthreads();
    }
    if (threadIdx.x == 0) out[b * 2 + c] = red[0] + bf3[c];
}

// ---------------------------------------------------------------------------
// launch
// ---------------------------------------------------------------------------
extern "C" void kernel_launch(void* const* d_in, const int* in_sizes, int n_in,
                              void* d_out, int out_size)
{
    const float* x1  = (const float*)d_in[0];
    const float* x2  = (const float*)d_in[1];
    const float* w1  = (const float*)d_in[2];
    const float* b1  = (const float*)d_in[3];
    const float* Wa  = (const float*)d_in[4];
    const float* ba  = (const float*)d_in[5];
    const float* Wb  = (const float*)d_in[6];
    const float* bb  = (const float*)d_in[7];
    const float* Wc  = (const float*)d_in[8];
    const float* bc  = (const float*)d_in[9];
    const float* lw  = (const float*)d_in[10];
    const float* lb  = (const float*)d_in[11];
    const float* w5  = (const float*)d_in[12];
    const float* b5  = (const float*)d_in[13];
    const float* w6  = (const float*)d_in[14];
    const float* b6  = (const float*)d_in[15];
    const float* Wf1 = (const float*)d_in[16];
    const float* bf1 = (const float*)d_in[17];
    const float* Wf2 = (const float*)d_in[18];
    const float* bf2 = (const float*)d_in[19];
    const float* Wf3 = (const float*)d_in[20];
    const float* bf3 = (const float*)d_in[21];
    float* out = (float*)d_out;

    float* S = nullptr;
    cudaGetSymbolAddress((void**)&S, g_scratch);
    float* A4   = S + OFF_A4;
    float* h1   = S + OFF_H1;
    float* h2   = S + OFF_H2;
    float* dynw = S + OFF_DYNW;
    float* y1   = S + OFF_Y1;
    float* cat  = S + OFF_CAT;
    float* z1   = S + OFF_Z1;
    float* z2   = S + OFF_Z2;
    float* part = S + OFF_PART;

    // branch a front
    k_a_front<<<dim3(20, 64), 256>>>(x1, w1, b1, A4);

    // h1 = relu(A4 @ Wa + ba)   [K=4899, N=1000] split-tf32, splitK=16
    gemm64<true><<<dim3(8, 16), 256>>>(A4, Wa, part, 4899, 1000, 16);
    epilogue<<<(64 * 1000 + 255) / 256, 256>>>(part, ba, h1, 1000, 16, 1);

    // h2 = relu(h1 @ Wb + bb)   [K=1000, N=500] split-tf32, splitK=16
    gemm64<true><<<dim3(4, 16), 256>>>(h1, Wb, part, 1000, 500, 16);
    epilogue<<<(64 * 500 + 255) / 256, 256>>>(part, bb, h2, 500, 16, 1);

    // dynamic weights + per-sample conv -> cat[:, 0:2450]
    k_dynw<<<3, 256>>>(h2, Wc, bc, lw, dynw);
    k_dynconv<<<dim3(10, 64), 256>>>(x1, dynw, lb, cat);

    // branch b -> cat[:, 2450:]
    k_b1<<<dim3(39, 64), 256>>>(x2, w5, b5, y1);
    k_b2<<<dim3(51, 64), 256>>>(y1, w6, b6, cat);

    // z1 = relu(cat @ Wf1 + bf1) [K=15506, N=8000] single tf32, splitK=2
    gemm64<false><<<dim3(63, 2), 256>>>(cat, Wf1, part, 15506, 8000, 2);
    epilogue<<<(64 * 8000 + 255) / 256, 256>>>(part, bf1, z1, 8000, 2, 1);

    // z2 = relu(z1 @ Wf2 + bf2)  [K=8000, N=2000] split-tf32, splitK=8
    gemm64<true><<<dim3(16, 8), 256>>>(z1, Wf2, part, 8000, 2000, 8);
    epilogue<<<(64 * 2000 + 255) / 256, 256>>>(part, bf2, z2, 2000, 8, 1);

    // out = z2 @ Wf3 + bf3
    k_final<<<128, 128>>>(z2, Wf3, bf3, out);
}

// round 9
// speedup vs baseline: 1.0719x; 1.0019x over previous
#include <cuda_runtime.h>
#include <cuda_bf16.h>
#include <cstdint>

// ---------------------------------------------------------------------------
// Scratch (single static device buffer, offsets in floats)
// ---------------------------------------------------------------------------
#define OFF_A4    0              // 64*4899  = 313536
#define OFF_H1    313536         // 64*1000  = 64000
#define OFF_H2    377536         // 64*500   = 32000
#define OFF_DYNW  409536         // 64*9     = 576
#define OFF_Y1    410112         // 64*2*4900= 627200
#define OFF_CAT   1037312        // 64*15506 = 992384
#define OFF_Z1    2029696        // 64*8000  = 512000
#define OFF_Z2    2541696        // 64*2000  = 128000
#define OFF_PART  2669696        // up to 16*64*1000 / 2*64*8000 / 8*64*2000 = 1.024M
#define SCRATCH_FLOATS 3800000

__device__ float g_scratch[SCRATCH_FLOATS];

// ---------------------------------------------------------------------------
// TF32 helpers
// ---------------------------------------------------------------------------
__device__ __forceinline__ uint32_t f2tf(float x) {
    uint32_t r;
    asm("cvt.rna.tf32.f32 %0, %1;" : "=r"(r) : "f"(x));
    return r;
}

__device__ __forceinline__ void mma_tf32(float* c, const uint32_t* a,
                                         uint32_t b0, uint32_t b1) {
    asm("mma.sync.aligned.m16n8k8.row.col.f32.tf32.tf32.f32 "
        "{%0,%1,%2,%3},{%4,%5,%6,%7},{%8,%9},{%0,%1,%2,%3};"
        : "+f"(c[0]), "+f"(c[1]), "+f"(c[2]), "+f"(c[3])
        : "r"(a[0]), "r"(a[1]), "r"(a[2]), "r"(a[3]), "r"(b0), "r"(b1));
}

// ---------------------------------------------------------------------------
// GEMM: C_part[s] = A(64 x K) @ B(K x N), row-major both.
// 256 threads = 8 warps. Warp computes all 64 rows x 16 cols (2 n8-tiles).
// CTA covers 128 cols. gridDim.y = splitK; each split writes its own
// disjoint partial slab (deterministic, no atomics).
// SPLIT=true: 3-term split-TF32 (near-fp32 accuracy).
// ---------------------------------------------------------------------------
template <bool SPLIT>
__global__ __launch_bounds__(256) void gemm64(
    const float* __restrict__ A, const float* __restrict__ B,
    float* __restrict__ part, int K, int N, int splitk)
{
    const int warp = threadIdx.x >> 5;
    const int lane = threadIdx.x & 31;
    const int grp  = lane >> 2;      // 0..7
    const int qid  = lane & 3;       // 0..3
    const int nb   = blockIdx.x * 128 + warp * 16;
    const int s    = blockIdx.y;
    const int kchunk = (K + splitk - 1) / splitk;
    const int k0 = s * kchunk;
    const int k1 = min(K, k0 + kchunk);

    float acc[4][2][4];
#pragma unroll
    for (int t = 0; t < 4; t++)
#pragma unroll
        for (int j = 0; j < 2; j++)
#pragma unroll
            for (int i = 0; i < 4; i++) acc[t][j][i] = 0.f;

    const int n0 = nb + grp;
    const int n1 = nb + 8 + grp;
    const bool pn0 = n0 < N;
    const bool pn1 = n1 < N;

    for (int kk = k0; kk < k1; kk += 8) {
        const int c0 = kk + qid;
        const int c1 = c0 + 4;
        const bool p0 = c0 < k1;
        const bool p1 = c1 < k1;

        // ---- B fragment loads (streaming; 100% sector efficiency) ----
        float fb[2][2];
        fb[0][0] = (p0 && pn0) ? B[(size_t)c0 * N + n0] : 0.f;
        fb[0][1] = (p1 && pn0) ? B[(size_t)c1 * N + n0] : 0.f;
        fb[1][0] = (p0 && pn1) ? B[(size_t)c0 * N + n1] : 0.f;
        fb[1][1] = (p1 && pn1) ? B[(size_t)c1 * N + n1] : 0.f;

        // ---- A fragment loads (L2-resident activations) ----
        float fa[4][4];
#pragma unroll
        for (int t = 0; t < 4; t++) {
            const float* Ar = A + (size_t)(t * 16 + grp) * K;
            fa[t][0] = p0 ? Ar[c0]         : 0.f;
            fa[t][1] = p0 ? Ar[8 * (size_t)K + c0] : 0.f;
            fa[t][2] = p1 ? Ar[c1]         : 0.f;
            fa[t][3] = p1 ? Ar[8 * (size_t)K + c1] : 0.f;
        }

        uint32_t bhi[2][2], ahi[4][4];
#pragma unroll
        for (int j = 0; j < 2; j++) {
            bhi[j][0] = f2tf(fb[j][0]);
            bhi[j][1] = f2tf(fb[j][1]);
        }
#pragma unroll
        for (int t = 0; t < 4; t++)
#pragma unroll
            for (int i = 0; i < 4; i++) ahi[t][i] = f2tf(fa[t][i]);

        if (SPLIT) {
            uint32_t blo[2][2], alo[4][4];
#pragma unroll
            for (int j = 0; j < 2; j++)
#pragma unroll
                for (int i = 0; i < 2; i++)
                    blo[j][i] = f2tf(fb[j][i] - __uint_as_float(bhi[j][i]));
#pragma unroll
            for (int t = 0; t < 4; t++)
#pragma unroll
                for (int i = 0; i < 4; i++)
                    alo[t][i] = f2tf(fa[t][i] - __uint_as_float(ahi[t][i]));
#pragma unroll
            for (int t = 0; t < 4; t++) {
#pragma unroll
                for (int j = 0; j < 2; j++) {
                    mma_tf32(acc[t][j], alo[t], bhi[j][0], bhi[j][1]);
                    mma_tf32(acc[t][j], ahi[t], blo[j][0], blo[j][1]);
                    mma_tf32(acc[t][j], ahi[t], bhi[j][0], bhi[j][1]);
                }
            }
        } else {
#pragma unroll
            for (int t = 0; t < 4; t++)
#pragma unroll
                for (int j = 0; j < 2; j++)
                    mma_tf32(acc[t][j], ahi[t], bhi[j][0], bhi[j][1]);
        }
    }

    // ---- store partials ----
#pragma unroll
    for (int t = 0; t < 4; t++) {
#pragma unroll
        for (int j = 0; j < 2; j++) {
            const int col = nb + 8 * j + 2 * qid;
            const int row = t * 16 + grp;
            float* p = part + (size_t)(s * 64 + row) * N + col;
            if (col < N) {
                p[0]               = acc[t][j][0];
                p[(size_t)8 * N]   = acc[t][j][2];
            }
            if (col + 1 < N) {
                p[1]                 = acc[t][j][1];
                p[(size_t)8 * N + 1] = acc[t][j][3];
            }
        }
    }
}

// Reduce splitK partials + bias (+ReLU)
__global__ void epilogue(const float* __restrict__ part,
                         const float* __restrict__ bias,
                         float* __restrict__ out, int N, int splitk, int do_relu)
{
    int idx = blockIdx.x * blockDim.x + threadIdx.x;
    if (idx >= 64 * N) return;
    int row = idx / N, col = idx - row * N;
    float s = bias[col];
    for (int p = 0; p < splitk; p++)
        s += part[(size_t)(p * 64 + row) * N + col];
    out[idx] = do_relu ? fmaxf(s, 0.f) : s;
}

// ---------------------------------------------------------------------------
// Elementwise / small kernels
// ---------------------------------------------------------------------------

// 3x3 conv at (h, wpos) over a 2x4900 image with pad 1
__device__ __forceinline__ float conv3(const float* X, const float* w,
                                       float bias, int h, int wpos)
{
    float s = bias;
#pragma unroll
    for (int dh = 0; dh < 3; dh++) {
        int ih = h + dh - 1;
        if (ih < 0 || ih > 1) continue;
        const float* R = X + ih * 4900;
#pragma unroll
        for (int dw = 0; dw < 3; dw++) {
            int iw = wpos + dw - 1;
            if (iw >= 0 && iw < 4900) s += R[iw] * w[dh * 3 + dw];
        }
    }
    return s;
}

// branch a front: conv(w1,pad1)+b1 -> relu -> maxpool 2x2 s1 -> A4 (64,4899)
__global__ void k_a_front(const float* __restrict__ x1,
                          const float* __restrict__ w1,
                          const float* __restrict__ b1,
                          float* __restrict__ A4)
{
    int j = blockIdx.x * blockDim.x + threadIdx.x;
    int b = blockIdx.y;
    if (j >= 4899) return;
    const float* X = x1 + (size_t)b * 9800;
    float w[9];
#pragma unroll
    for (int i = 0; i < 9; i++) w[i] = w1[i];
    float bias = b1[0];
    float m = conv3(X, w, bias, 0, j);
    m = fmaxf(m, conv3(X, w, bias, 0, j + 1));
    m = fmaxf(m, conv3(X, w, bias, 1, j));
    m = fmaxf(m, conv3(X, w, bias, 1, j + 1));
    A4[(size_t)b * 4899 + j] = fmaxf(m, 0.f);
}

// a3 = h2 @ Wc + bc ; dynw = lw * a3   (64 x 9 outputs, K=500)
__global__ void k_dynw(const float* __restrict__ h2,
                       const float* __restrict__ Wc,
                       const float* __restrict__ bc,
                       const float* __restrict__ lw,
                       float* __restrict__ dynw)
{
    int t = blockIdx.x * blockDim.x + threadIdx.x;
    if (t >= 64 * 9) return;
    int b = t / 9, i = t - b * 9;
    const float* H = h2 + b * 500;
    float s = bc[i];
    for (int k = 0; k < 500; k++) s += H[k] * Wc[k * 9 + i];
    dynw[t] = s * lw[t];
}

// per-sample dynamic 3x3 conv + lb -> relu -> maxpool 2x2 s2 -> cat[:, 0:2450]
__global__ void k_dynconv(const float* __restrict__ x1,
                          const float* __restrict__ dynw,
                          const float* __restrict__ lb,
                          float* __restrict__ cat)
{
    int j = blockIdx.x * blockDim.x + threadIdx.x;
    int b = blockIdx.y;
    if (j >= 2450) return;
    const float* X = x1 + (size_t)b * 9800;
    float w[9];
#pragma unroll
    for (int i = 0; i < 9; i++) w[i] = dynw[b * 9 + i];
    float bias = lb[b];
    float m = conv3(X, w, bias, 0, 2 * j);
    m = fmaxf(m, conv3(X, w, bias, 0, 2 * j + 1));
    m = fmaxf(m, conv3(X, w, bias, 1, 2 * j));
    m = fmaxf(m, conv3(X, w, bias, 1, 2 * j + 1));
    cat[(size_t)b * 15506 + j] = fmaxf(m, 0.f);
}

// 2x2 conv at (hh in 0..2, ww in 0..4900) over 2x4900 image, pad 1
__device__ __forceinline__ float conv2x2(const float* X, const float* w,
                                         float bias, int hh, int ww)
{
    float s = bias;
#pragma unroll
    for (int dh = 0; dh < 2; dh++) {
        int ih = hh - 1 + dh;
        if (ih < 0 || ih > 1) continue;
        const float* R = X + ih * 4900;
#pragma unroll
        for (int dw = 0; dw < 2; dw++) {
            int iw = ww - 1 + dw;
            if (iw >= 0 && iw < 4900) s += R[iw] * w[dh * 2 + dw];
        }
    }
    return s;
}

// branch b stage 1: conv(w5,pad1)+b5 -> relu -> maxpool 2x2 s1 -> y1 (64,2,4900)
__global__ void k_b1(const float* __restrict__ x2,
                     const float* __restrict__ w5,
                     const float* __restrict__ b5,
                     float* __restrict__ y1)
{
    int idx = blockIdx.x * blockDim.x + threadIdx.x;
    int b = blockIdx.y;
    if (idx >= 9800) return;
    int h = idx / 4900, w = idx - h * 4900;
    const float* X = x2 + (size_t)b * 9800;
    float wk[4];
#pragma unroll
    for (int i = 0; i < 4; i++) wk[i] = w5[i];
    float bias = b5[0];
    float m = conv2x2(X, wk, bias, h, w);
    m = fmaxf(m, conv2x2(X, wk, bias, h, w + 1));
    m = fmaxf(m, conv2x2(X, wk, bias, h + 1, w));
    m = fmaxf(m, conv2x2(X, wk, bias, h + 1, w + 1));
    y1[(size_t)b * 9800 + idx] = fmaxf(m, 0.f);
}

// branch b stage 2: conv(w6, s2)+b6 -> relu -> maxpool (1,6) s6 -> cat[:, 2450:]
__global__ void k_b2(const float* __restrict__ y1,
                     const float* __restrict__ w6,
                     const float* __restrict__ b6,
                     float* __restrict__ cat)
{
    int t = blockIdx.x * blockDim.x + threadIdx.x;
    int b = blockIdx.y;
    if (t >= 32 * 408) return;
    int c = t / 408, j = t - c * 408;
    float w0 = w6[c * 4 + 0], w1v = w6[c * 4 + 1];
    float w2 = w6[c * 4 + 2], w3 = w6[c * 4 + 3];
    float bias = b6[c];
    const float* Y0 = y1 + (size_t)b * 9800;
    const float* Y1 = Y0 + 4900;
    float m = -3.4e38f;
#pragma unroll
    for (int tt = 0; tt < 6; tt++) {
        int wp = 6 * j + tt;  // <= 2447 < 2450
        float s = bias + Y0[2 * wp] * w0 + Y0[2 * wp + 1] * w1v
                       + Y1[2 * wp] * w2 + Y1[2 * wp + 1] * w3;
        m = fmaxf(m, s);
    }
    cat[(size_t)b * 15506 + 2450 + t] = fmaxf(m, 0.f);
}

// final: out(64,2) = z2(64,2000) @ Wf3(2000,2) + bf3 (exact fp32 block-reduce)
__global__ void k_final(const float* __restrict__ z2,
                        const float* __restrict__ Wf3,
                        const float* __restrict__ bf3,
                        float* __restrict__ out)
{
    int b = blockIdx.x >> 1;
    int c = blockIdx.x & 1;
    const float* Z = z2 + b * 2000;
    float s = 0.f;
    for (int k = threadIdx.x; k < 2000; k += 128)
        s += Z[k] * Wf3[2 * k + c];
    __shared__ float red[128];
    red[threadIdx.x] = s;
    __syncthreads();
    for (int d = 64; d > 0; d >>= 1) {
        if (threadIdx.x < d) red[threadIdx.x] += red[threadIdx.x + d];
        __syncthreads();
    }
    if (threadIdx.x == 0) out[b * 2 + c] = red[0] + bf3[c];
}

// ---------------------------------------------------------------------------
// launch
// ---------------------------------------------------------------------------
extern "C" void kernel_launch(void* const* d_in, const int* in_sizes, int n_in,
                              void* d_out, int out_size)
{
    const float* x1  = (const float*)d_in[0];
    const float* x2  = (const float*)d_in[1];
    const float* w1  = (const float*)d_in[2];
    const float* b1  = (const float*)d_in[3];
    const float* Wa  = (const float*)d_in[4];
    const float* ba  = (const float*)d_in[5];
    const float* Wb  = (const float*)d_in[6];
    const float* bb  = (const float*)d_in[7];
    const float* Wc  = (const float*)d_in[8];
    const float* bc  = (const float*)d_in[9];
    const float* lw  = (const float*)d_in[10];
    const float* lb  = (const float*)d_in[11];
    const float* w5  = (const float*)d_in[12];
    const float* b5  = (const float*)d_in[13];
    const float* w6  = (const float*)d_in[14];
    const float* b6  = (const float*)d_in[15];
    const float* Wf1 = (const float*)d_in[16];
    const float* bf1 = (const float*)d_in[17];
    const float* Wf2 = (const float*)d_in[18];
    const float* bf2 = (const float*)d_in[19];
    const float* Wf3 = (const float*)d_in[20];
    const float* bf3 = (const float*)d_in[21];
    float* out = (float*)d_out;

    float* S = nullptr;
    cudaGetSymbolAddress((void**)&S, g_scratch);
    float* A4   = S + OFF_A4;
    float* h1   = S + OFF_H1;
    float* h2   = S + OFF_H2;
    float* dynw = S + OFF_DYNW;
    float* y1   = S + OFF_Y1;
    float* cat  = S + OFF_CAT;
    float* z1   = S + OFF_Z1;
    float* z2   = S + OFF_Z2;
    float* part = S + OFF_PART;

    // branch a front
    k_a_front<<<dim3(20, 64), 256>>>(x1, w1, b1, A4);

    // h1 = relu(A4 @ Wa + ba)   [K=4899, N=1000] split-tf32, splitK=16
    gemm64<true><<<dim3(8, 16), 256>>>(A4, Wa, part, 4899, 1000, 16);
    epilogue<<<(64 * 1000 + 255) / 256, 256>>>(part, ba, h1, 1000, 16, 1);

    // h2 = relu(h1 @ Wb + bb)   [K=1000, N=500] split-tf32, splitK=16
    gemm64<true><<<dim3(4, 16), 256>>>(h1, Wb, part, 1000, 500, 16);
    epilogue<<<(64 * 500 + 255) / 256, 256>>>(part, bb, h2, 500, 16, 1);

    // dynamic weights + per-sample conv -> cat[:, 0:2450]
    k_dynw<<<3, 256>>>(h2, Wc, bc, lw, dynw);
    k_dynconv<<<dim3(10, 64), 256>>>(x1, dynw, lb, cat);

    // branch b -> cat[:, 2450:]
    k_b1<<<dim3(39, 64), 256>>>(x2, w5, b5, y1);
    k_b2<<<dim3(51, 64), 256>>>(y1, w6, b6, cat);

    // z1 = relu(cat @ Wf1 + bf1) [K=15506, N=8000] single tf32, splitK=2
    gemm64<false><<<dim3(63, 2), 256>>>(cat, Wf1, part, 15506, 8000, 2);
    epilogue<<<(64 * 8000 + 255) / 256, 256>>>(part, bf1, z1, 8000, 2, 1);

    // z2 = relu(z1 @ Wf2 + bf2)  [K=8000, N=2000] split-tf32, splitK=8
    gemm64<true><<<dim3(16, 8), 256>>>(z1, Wf2, part, 8000, 2000, 8);
    epilogue<<<(64 * 2000 + 255) / 256, 256>>>(part, bf2, z2, 2000, 8, 1);

    // out = z2 @ Wf3 + bf3
    k_final<<<128, 128>>>(z2, Wf3, bf3, out);
}